// round 10
// baseline (speedup 1.0000x reference)
#include <cuda_runtime.h>
#include <cuda_bf16.h>
#include <cstdint>

#define BS_     4096
#define IN_DIM_ 2048
#define NN_     16384
#define DTOT_   129
#define KD_     144          // logical K of big GEMM (129 padded to 144)
#define KP2     448          // tripled K (3*144) padded to 448
#define PK      2048         // proj inner dim
#define PN      192          // proj output dim padded (>=129)
#define PSPLIT  8
#define PCH     (PK / PSPLIT)   // 256
#define INV_SQRT_N_ 0.0078125f
#define SQRT2_      1.41421356237309515f

__device__ __nv_bfloat16 Xh[BS_ * PK], Xl[BS_ * PK];
__device__ __nv_bfloat16 Wh2[PN * PK], Wl2[PN * PK];
__device__ float         Pp[PSPLIT * BS_ * PN];
__device__ __nv_bfloat16 A2[BS_ * KP2];     // [b][k'] = [Ah | Ah | Al | 0]
__device__ __nv_bfloat16 B2[NN_ * KP2];     // [n][k'] = [Bh | Bl | Bh | 0]

// ---------------- PTX helpers ----------------
__device__ __forceinline__ uint32_t s2u(const void* p) {
    uint32_t a; asm("{.reg .u64 t; cvta.to.shared.u64 t,%1; cvt.u32.u64 %0,t;}" : "=r"(a) : "l"(p));
    return a;
}
#define CP_ASYNC16(dst, src) asm volatile("cp.async.cg.shared.global [%0], [%1], 16;" :: "r"(dst), "l"(src))
#define CP_COMMIT()          asm volatile("cp.async.commit_group;" ::: "memory")
#define CP_WAIT(n)           asm volatile("cp.async.wait_group %0;" :: "n"(n) : "memory")
#define LDSM4(r, addr) asm volatile("ldmatrix.sync.aligned.m8n8.x4.shared.b16 {%0,%1,%2,%3}, [%4];" \
    : "=r"((r)[0]), "=r"((r)[1]), "=r"((r)[2]), "=r"((r)[3]) : "r"(addr))
#define MMA16816(d, a, b) asm volatile( \
    "mma.sync.aligned.m16n8k16.row.col.f32.bf16.bf16.f32 " \
    "{%0,%1,%2,%3}, {%4,%5,%6,%7}, {%8,%9}, {%0,%1,%2,%3};" \
    : "+f"((d)[0]), "+f"((d)[1]), "+f"((d)[2]), "+f"((d)[3]) \
    : "r"((a)[0]), "r"((a)[1]), "r"((a)[2]), "r"((a)[3]), "r"((b)[0]), "r"((b)[1]))

union BF4 { __nv_bfloat16 b[4]; uint2 u; };

// ---------------- split x into bf16 hi/lo ----------------
__global__ __launch_bounds__(256) void split_x_kernel(const float* __restrict__ x)
{
    int id = blockIdx.x * 256 + threadIdx.x;           // over BS_*PK/4
    float4 v = ((const float4*)x)[id];
    float vv[4] = {v.x, v.y, v.z, v.w};
    BF4 h, l;
    #pragma unroll
    for (int i = 0; i < 4; i++) {
        h.b[i] = __float2bfloat16_rn(vv[i]);
        l.b[i] = __float2bfloat16_rn(vv[i] - __bfloat162float(h.b[i]));
    }
    ((uint2*)Xh)[id] = h.u;
    ((uint2*)Xl)[id] = l.u;
}

// ---------------- split W_proj into padded bf16 hi/lo [PN][PK] ----------------
__global__ __launch_bounds__(256) void split_w_kernel(const float* __restrict__ Wp)
{
    int id = blockIdx.x * 256 + threadIdx.x;           // over PN*PK/4
    int row = (id * 4) / PK;
    BF4 h, l;
    if (row < DTOT_) {
        float4 v = ((const float4*)Wp)[id];
        float vv[4] = {v.x, v.y, v.z, v.w};
        #pragma unroll
        for (int i = 0; i < 4; i++) {
            h.b[i] = __float2bfloat16_rn(vv[i]);
            l.b[i] = __float2bfloat16_rn(vv[i] - __bfloat162float(h.b[i]));
        }
    } else {
        #pragma unroll
        for (int i = 0; i < 4; i++) { h.b[i] = __float2bfloat16_rn(0.f); l.b[i] = h.b[i]; }
    }
    ((uint2*)Wh2)[id] = h.u;
    ((uint2*)Wl2)[id] = l.u;
}

// ---------------- proj via tensor cores: Pp[s] = x_tile @ W^T ----------------
#define QM 64
#define QSTG 32768

__global__ __launch_bounds__(256, 2) void proj_mma_kernel()
{
    extern __shared__ char sm[];
    const uint32_t sb = s2u(sm);
    const int tid = threadIdx.x, lane = tid & 31, wid = tid >> 5;
    const int wm = wid & 1, wn = wid >> 1;
    const int s = blockIdx.x;
    const int bm = blockIdx.y * QM;

    const int arow = wm * 32 + (lane & 15);
    const uint32_t arx = (uint32_t)((arow & 7) << 4);
    const uint32_t acb = (uint32_t)((lane >> 4) * 16);
    const int brow = wn * 48 + (lane & 7) + ((lane >> 4) & 1) * 8;
    const uint32_t brx = (uint32_t)((brow & 7) << 4);
    const uint32_t bcb = (uint32_t)(((lane >> 3) & 1) * 16);

    float acc[2][6][4] = {};

    auto load_tile = [&](int it, int stg) {
        int term = it >> 2;
        int k0 = s * PCH + (it & 3) * 64;
        const __nv_bfloat16* Ap = (term == 2) ? Xl : Xh;
        const __nv_bfloat16* Bp = (term == 1) ? Wl2 : Wh2;
        const char* gA = (const char*)(Ap + (size_t)bm * PK + k0);
        const char* gB = (const char*)(Bp + k0);
        uint32_t base = sb + stg * QSTG;
        #pragma unroll
        for (int t = 0; t < 2; t++) {
            int id = tid + t * 256, row = id >> 3, c = id & 7;
            uint32_t so = (uint32_t)(row * 128 + c * 16); so ^= (so >> 3) & 0x70;
            CP_ASYNC16(base + so, gA + (size_t)row * (PK * 2) + c * 16);
        }
        #pragma unroll
        for (int t = 0; t < 6; t++) {
            int id = tid + t * 256, row = id >> 3, c = id & 7;
            uint32_t so = (uint32_t)(row * 128 + c * 16); so ^= (so >> 3) & 0x70;
            CP_ASYNC16(base + 8192 + so, gB + (size_t)row * (PK * 2) + c * 16);
        }
        CP_COMMIT();
    };

    load_tile(0, 0);
    for (int it = 0; it < 12; it++) {
        if (it + 1 < 12) { load_tile(it + 1, (it + 1) & 1); CP_WAIT(1); }
        else CP_WAIT(0);
        __syncthreads();
        const uint32_t ab = sb + (it & 1) * QSTG;
        const uint32_t bb = ab + 8192;
        #pragma unroll
        for (int ks = 0; ks < 4; ks++) {
            uint32_t af[2][4], bf[3][4];
            #pragma unroll
            for (int mi = 0; mi < 2; mi++)
                LDSM4(af[mi], ab + (uint32_t)((arow + mi * 16) * 128) + ((ks * 32 + acb) ^ arx));
            #pragma unroll
            for (int nb = 0; nb < 3; nb++)
                LDSM4(bf[nb], bb + (uint32_t)((brow + nb * 16) * 128) + ((ks * 32 + bcb) ^ brx));
            #pragma unroll
            for (int mi = 0; mi < 2; mi++)
                #pragma unroll
                for (int ni = 0; ni < 6; ni++) {
                    uint32_t bp[2] = { bf[ni >> 1][(ni & 1) * 2], bf[ni >> 1][(ni & 1) * 2 + 1] };
                    MMA16816(acc[mi][ni], af[mi], bp);
                }
        }
        __syncthreads();
    }

    float* P = Pp + (size_t)s * BS_ * PN;
    #pragma unroll
    for (int mi = 0; mi < 2; mi++) {
        int m0 = bm + wm * 32 + mi * 16 + (lane >> 2);
        #pragma unroll
        for (int ni = 0; ni < 6; ni++) {
            int n0 = wn * 48 + ni * 8 + (lane & 3) * 2;
            *(float2*)(&P[(size_t)m0 * PN + n0])       = make_float2(acc[mi][ni][0], acc[mi][ni][1]);
            *(float2*)(&P[(size_t)(m0 + 8) * PN + n0]) = make_float2(acc[mi][ni][2], acc[mi][ni][3]);
        }
    }
}

// ---------------- finalize: sum partials + bias + scales -> A2 ----------------
__global__ __launch_bounds__(256) void finalize_kernel(const float* __restrict__ bp)
{
    int id = blockIdx.x * 256 + threadIdx.x;          // over BS_*KD_
    int b = id / KD_, d = id - b * KD_;
    float v = 0.f;
    if (d < DTOT_) {
        #pragma unroll
        for (int s = 0; s < PSPLIT; s++)
            v += Pp[((size_t)s * BS_ + b) * PN + d];
        v += bp[d];
        if (d == 0)       v *= INV_SQRT_N_;
        else if (d <= 64) v *= INV_SQRT_N_ * SQRT2_;
    }
    __nv_bfloat16 h = __float2bfloat16_rn(v);
    __nv_bfloat16 l = __float2bfloat16_rn(v - __bfloat162float(h));
    __nv_bfloat16* row = A2 + (size_t)b * KP2;
    row[d] = h; row[KD_ + d] = h; row[2*KD_ + d] = l;
    if (d < KP2 - 3*KD_) row[3*KD_ + d] = __float2bfloat16_rn(0.f);
}

// ---------------- build B2 = [Bh|Bl|Bh|0] ----------------
__global__ void build_B2_kernel(const float* __restrict__ Ws)
{
    int n = blockIdx.x, d = threadIdx.x;
    float v;
    if (d == 0) v = 1.0f;
    else if (d < 65) {
        int j = (d + 1) >> 1;
        int m = (j * n) & (NN_ - 1);
        float t = (float)(2 * m) * (1.0f / (float)NN_);
        float s, c; sincospif(t, &s, &c);
        v = (d & 1) ? c : s;
    } else if (d < DTOT_) v = Ws[(size_t)n * 64 + (d - 65)];
    else v = 0.f;
    __nv_bfloat16 h = __float2bfloat16_rn(v);
    __nv_bfloat16 l = __float2bfloat16_rn(v - __bfloat162float(h));
    __nv_bfloat16* row = B2 + (size_t)n * KP2;
    row[d] = h; row[KD_ + d] = l; row[2*KD_ + d] = h;
    if (d < KP2 - 3*KD_) row[3*KD_ + d] = __float2bfloat16_rn(0.f);
}

// ---------------- big GEMM: C = A2 @ B2^T ----------------
// BM=128, BN=256, BK=64; 8 warps (2m x 4n), warp tile 64x64; 3-stage cp.async
#define GM 128
#define GN 256
#define GK 64
#define NIT (KP2 / GK)          // 7
#define STG 49152               // per stage: A 16KB @ +0, B 32KB @ +16384

__global__ __launch_bounds__(256, 1) void gemm_kernel(float* __restrict__ C)
{
    extern __shared__ char sm[];
    const uint32_t sb = s2u(sm);
    const int tid = threadIdx.x, lane = tid & 31, wid = tid >> 5;
    const int wm = wid & 1, wn = wid >> 1;
    const int bm = blockIdx.y * GM, bn = blockIdx.x * GN;
    const char* gA = (const char*)(A2 + (size_t)bm * KP2);
    const char* gB = (const char*)(B2 + (size_t)bn * KP2);

    const int lrow = tid >> 3;           // 0..31
    const int lc = tid & 7;

    const int arow = wm * 64 + (lane & 15);
    const uint32_t arx = (uint32_t)((arow & 7) << 4);
    const uint32_t acb = (uint32_t)((lane >> 4) * 16);
    const int brow = wn * 64 + (lane & 7) + ((lane >> 4) & 1) * 8;
    const uint32_t brx = (uint32_t)((brow & 7) << 4);
    const uint32_t bcb = (uint32_t)(((lane >> 3) & 1) * 16);

    float acc[4][8][4] = {};

    auto load_tile = [&](int kt, int stg) {
        size_t koff = (size_t)kt * GK * 2;
        uint32_t base = sb + stg * STG;
        #pragma unroll
        for (int t = 0; t < 4; t++) {            // A: 128 rows
            int row = lrow + t * 32;
            uint32_t so = (uint32_t)(row * 128 + lc * 16); so ^= (so >> 3) & 0x70;
            CP_ASYNC16(base + so, gA + (size_t)row * (KP2*2) + koff + lc * 16);
        }
        #pragma unroll
        for (int t = 0; t < 8; t++) {            // B: 256 rows
            int row = lrow + t * 32;
            uint32_t so = (uint32_t)(row * 128 + lc * 16); so ^= (so >> 3) & 0x70;
            CP_ASYNC16(base + 16384 + so, gB + (size_t)row * (KP2*2) + koff + lc * 16);
        }
        CP_COMMIT();
    };

    load_tile(0, 0);
    load_tile(1, 1);

    int st = 0;
    for (int kt = 0; kt < NIT; kt++) {
        if (kt + 2 < NIT) { load_tile(kt + 2, (kt + 2) % 3); CP_WAIT(2); }
        else if (kt + 1 < NIT) CP_WAIT(1);
        else CP_WAIT(0);
        __syncthreads();

        const uint32_t ab = sb + st * STG;
        const uint32_t bb = ab + 16384;

        uint32_t af[2][4][4], bf[2][4][4];
        #pragma unroll
        for (int mi = 0; mi < 4; mi++)
            LDSM4(af[0][mi], ab + (uint32_t)((arow + mi * 16) * 128) + ((0 + acb) ^ arx));
        #pragma unroll
        for (int nb = 0; nb < 4; nb++)
            LDSM4(bf[0][nb], bb + (uint32_t)((brow + nb * 16) * 128) + ((0 + bcb) ^ brx));

        #pragma unroll
        for (int ks = 0; ks < 4; ks++) {
            const int cur = ks & 1, nxt = cur ^ 1;
            if (ks < 3) {
                #pragma unroll
                for (int mi = 0; mi < 4; mi++)
                    LDSM4(af[nxt][mi], ab + (uint32_t)((arow + mi * 16) * 128) + (((ks + 1) * 32 + acb) ^ arx));
                #pragma unroll
                for (int nb = 0; nb < 4; nb++)
                    LDSM4(bf[nxt][nb], bb + (uint32_t)((brow + nb * 16) * 128) + (((ks + 1) * 32 + bcb) ^ brx));
            }
            #pragma unroll
            for (int mi = 0; mi < 4; mi++)
                #pragma unroll
                for (int ni = 0; ni < 8; ni++) {
                    uint32_t bp[2] = { bf[cur][ni >> 1][(ni & 1) * 2], bf[cur][ni >> 1][(ni & 1) * 2 + 1] };
                    MMA16816(acc[mi][ni], af[cur][mi], bp);
                }
        }
        __syncthreads();
        st = (st + 1 == 3) ? 0 : st + 1;
    }

    #pragma unroll
    for (int mi = 0; mi < 4; mi++) {
        int m0 = bm + wm * 64 + mi * 16 + (lane >> 2);
        #pragma unroll
        for (int ni = 0; ni < 8; ni++) {
            int n0 = bn + wn * 64 + ni * 8 + (lane & 3) * 2;
            *(float2*)(&C[(size_t)m0 * NN_ + n0])       = make_float2(acc[mi][ni][0], acc[mi][ni][1]);
            *(float2*)(&C[(size_t)(m0 + 8) * NN_ + n0]) = make_float2(acc[mi][ni][2], acc[mi][ni][3]);
        }
    }
}

// ---------------- launch ----------------
extern "C" void kernel_launch(void* const* d_in, const int* in_sizes, int n_in,
                              void* d_out, int out_size)
{
    const float* x  = (const float*)d_in[0];
    const float* Wp = (const float*)d_in[1];
    const float* bp = (const float*)d_in[2];
    const float* Ws = (const float*)d_in[3];
    float* out = (float*)d_out;

    cudaFuncSetAttribute(gemm_kernel,     cudaFuncAttributeMaxDynamicSharedMemorySize, 3 * STG);
    cudaFuncSetAttribute(proj_mma_kernel, cudaFuncAttributeMaxDynamicSharedMemorySize, 2 * QSTG);

    split_x_kernel<<<(BS_ * PK / 4) / 256, 256>>>(x);
    split_w_kernel<<<(PN * PK / 4) / 256, 256>>>(Wp);
    proj_mma_kernel<<<dim3(PSPLIT, BS_ / QM), 256, 2 * QSTG>>>();
    finalize_kernel<<<(BS_ * KD_) / 256, 256>>>(bp);
    build_B2_kernel<<<NN_, KD_>>>(Ws);
    gemm_kernel<<<dim3(NN_ / GN, BS_ / GM), 256, 3 * STG>>>(out);
}

// round 13
// speedup vs baseline: 1.4288x; 1.4288x over previous
#include <cuda_runtime.h>
#include <cuda_bf16.h>
#include <cstdint>

#define BS_     4096
#define IN_DIM_ 2048
#define NN_     16384
#define DTOT_   129
#define KPP     256          // packed GEMM K: 129 AhBh + 65 AlBh + 62 AhBl
#define PK      2048
#define PN      192
#define PSPLIT  8
#define PCH     (PK / PSPLIT)
#define INV_SQRT_N_ 0.0078125f
#define SQRT2_      1.41421356237309515f

__device__ __nv_bfloat16 Xh[BS_ * PK], Xl[BS_ * PK];
__device__ __nv_bfloat16 Wh2[PN * PK], Wl2[PN * PK];
__device__ float         Pp[PSPLIT * BS_ * PN];
__device__ __nv_bfloat16 A2[BS_ * KPP];
__device__ __nv_bfloat16 B2[NN_ * KPP];

// ---------------- PTX helpers ----------------
__device__ __forceinline__ uint32_t s2u(const void* p) {
    uint32_t a; asm("{.reg .u64 t; cvta.to.shared.u64 t,%1; cvt.u32.u64 %0,t;}" : "=r"(a) : "l"(p));
    return a;
}
#define CP_ASYNC16(dst, src) asm volatile("cp.async.cg.shared.global [%0], [%1], 16;" :: "r"(dst), "l"(src))
#define CP_COMMIT()          asm volatile("cp.async.commit_group;" ::: "memory")
#define CP_WAIT(n)           asm volatile("cp.async.wait_group %0;" :: "n"(n) : "memory")
#define LDSM4(r, addr) asm volatile("ldmatrix.sync.aligned.m8n8.x4.shared.b16 {%0,%1,%2,%3}, [%4];" \
    : "=r"((r)[0]), "=r"((r)[1]), "=r"((r)[2]), "=r"((r)[3]) : "r"(addr))
#define MMA16816(d, a, b) asm volatile( \
    "mma.sync.aligned.m16n8k16.row.col.f32.bf16.bf16.f32 " \
    "{%0,%1,%2,%3}, {%4,%5,%6,%7}, {%8,%9}, {%0,%1,%2,%3};" \
    : "+f"((d)[0]), "+f"((d)[1]), "+f"((d)[2]), "+f"((d)[3]) \
    : "r"((a)[0]), "r"((a)[1]), "r"((a)[2]), "r"((a)[3]), "r"((b)[0]), "r"((b)[1]))

union BF4 { __nv_bfloat16 b[4]; uint2 u; };

// Packed-column map: seg 0 = Ah*Bh, 1 = Al*Bh, 2 = Ah*Bl
__device__ __forceinline__ void colmap(int c, int& d, int& seg) {
    if (c < 129)      { d = c;              seg = 0; }
    else if (c == 129){ d = 0;              seg = 1; }
    else if (c < 194) { d = 65 + (c - 130); seg = 1; }
    else              { d = 65 + (c - 194); seg = 2; }
}

// ---------------- prep: split_x + split_w + build B2 (one launch) ----------------
#define SPLITX_BLKS ((BS_ * PK / 4) / 256)   // 8192
#define SPLITW_BLKS ((PN * PK / 4) / 256)    // 384

__global__ __launch_bounds__(256) void prep_kernel(const float* __restrict__ x,
                                                   const float* __restrict__ Wp,
                                                   const float* __restrict__ Ws)
{
    int blk = blockIdx.x, tid = threadIdx.x;
    if (blk < SPLITX_BLKS) {
        int id = blk * 256 + tid;
        float4 v = ((const float4*)x)[id];
        float vv[4] = {v.x, v.y, v.z, v.w};
        BF4 h, l;
        #pragma unroll
        for (int i = 0; i < 4; i++) {
            h.b[i] = __float2bfloat16_rn(vv[i]);
            l.b[i] = __float2bfloat16_rn(vv[i] - __bfloat162float(h.b[i]));
        }
        ((uint2*)Xh)[id] = h.u;
        ((uint2*)Xl)[id] = l.u;
    } else if (blk < SPLITX_BLKS + SPLITW_BLKS) {
        int id = (blk - SPLITX_BLKS) * 256 + tid;
        int row = (id * 4) / PK;
        BF4 h, l;
        if (row < DTOT_) {
            float4 v = ((const float4*)Wp)[id];
            float vv[4] = {v.x, v.y, v.z, v.w};
            #pragma unroll
            for (int i = 0; i < 4; i++) {
                h.b[i] = __float2bfloat16_rn(vv[i]);
                l.b[i] = __float2bfloat16_rn(vv[i] - __bfloat162float(h.b[i]));
            }
        } else {
            #pragma unroll
            for (int i = 0; i < 4; i++) { h.b[i] = __float2bfloat16_rn(0.f); l.b[i] = h.b[i]; }
        }
        ((uint2*)Wh2)[id] = h.u;
        ((uint2*)Wl2)[id] = l.u;
    } else {
        // build B2: one block per n, thread = packed column
        int n = blk - SPLITX_BLKS - SPLITW_BLKS;
        int c = tid;
        int d, seg; colmap(c, d, seg);
        float v;
        if (d == 0) v = 1.0f;
        else if (d < 65) {
            int j = (d + 1) >> 1;
            int m = (j * n) & (NN_ - 1);
            float t = (float)(2 * m) * (1.0f / (float)NN_);
            float s, cc; sincospif(t, &s, &cc);
            v = (d & 1) ? cc : s;
        } else v = Ws[(size_t)n * 64 + (d - 65)];
        __nv_bfloat16 h = __float2bfloat16_rn(v);
        __nv_bfloat16 out = (seg == 2) ? __float2bfloat16_rn(v - __bfloat162float(h)) : h;
        B2[(size_t)n * KPP + c] = out;
    }
}

// ---------------- proj via tensor cores (split-K x8, bf16x3) ----------------
#define QM 64
#define QSTG 32768

__global__ __launch_bounds__(256, 2) void proj_mma_kernel()
{
    extern __shared__ char sm[];
    const uint32_t sb = s2u(sm);
    const int tid = threadIdx.x, lane = tid & 31, wid = tid >> 5;
    const int wm = wid & 1, wn = wid >> 1;
    const int s = blockIdx.x;
    const int bm = blockIdx.y * QM;

    const int arow = wm * 32 + (lane & 15);
    const uint32_t arx = (uint32_t)((arow & 7) << 4);
    const uint32_t acb = (uint32_t)((lane >> 4) * 16);
    const int brow = wn * 48 + (lane & 7) + ((lane >> 4) & 1) * 8;
    const uint32_t brx = (uint32_t)((brow & 7) << 4);
    const uint32_t bcb = (uint32_t)(((lane >> 3) & 1) * 16);

    float acc[2][6][4] = {};

    auto load_tile = [&](int it, int stg) {
        int term = it >> 2;
        int k0 = s * PCH + (it & 3) * 64;
        const __nv_bfloat16* Ap = (term == 2) ? Xl : Xh;
        const __nv_bfloat16* Bp = (term == 1) ? Wl2 : Wh2;
        const char* gA = (const char*)(Ap + (size_t)bm * PK + k0);
        const char* gB = (const char*)(Bp + k0);
        uint32_t base = sb + stg * QSTG;
        #pragma unroll
        for (int t = 0; t < 2; t++) {
            int id = tid + t * 256, row = id >> 3, c = id & 7;
            uint32_t so = (uint32_t)(row * 128 + c * 16); so ^= (so >> 3) & 0x70;
            CP_ASYNC16(base + so, gA + (size_t)row * (PK * 2) + c * 16);
        }
        #pragma unroll
        for (int t = 0; t < 6; t++) {
            int id = tid + t * 256, row = id >> 3, c = id & 7;
            uint32_t so = (uint32_t)(row * 128 + c * 16); so ^= (so >> 3) & 0x70;
            CP_ASYNC16(base + 8192 + so, gB + (size_t)row * (PK * 2) + c * 16);
        }
        CP_COMMIT();
    };

    load_tile(0, 0);
    for (int it = 0; it < 12; it++) {
        if (it + 1 < 12) { load_tile(it + 1, (it + 1) & 1); CP_WAIT(1); }
        else CP_WAIT(0);
        __syncthreads();
        const uint32_t ab = sb + (it & 1) * QSTG;
        const uint32_t bb = ab + 8192;
        #pragma unroll
        for (int ks = 0; ks < 4; ks++) {
            uint32_t af[2][4], bf[3][4];
            #pragma unroll
            for (int mi = 0; mi < 2; mi++)
                LDSM4(af[mi], ab + (uint32_t)((arow + mi * 16) * 128) + ((ks * 32 + acb) ^ arx));
            #pragma unroll
            for (int nb = 0; nb < 3; nb++)
                LDSM4(bf[nb], bb + (uint32_t)((brow + nb * 16) * 128) + ((ks * 32 + bcb) ^ brx));
            #pragma unroll
            for (int mi = 0; mi < 2; mi++)
                #pragma unroll
                for (int ni = 0; ni < 6; ni++) {
                    uint32_t bp[2] = { bf[ni >> 1][(ni & 1) * 2], bf[ni >> 1][(ni & 1) * 2 + 1] };
                    MMA16816(acc[mi][ni], af[mi], bp);
                }
        }
        __syncthreads();
    }

    float* P = Pp + (size_t)s * BS_ * PN;
    #pragma unroll
    for (int mi = 0; mi < 2; mi++) {
        int m0 = bm + wm * 32 + mi * 16 + (lane >> 2);
        #pragma unroll
        for (int ni = 0; ni < 6; ni++) {
            int n0 = wn * 48 + ni * 8 + (lane & 3) * 2;
            *(float2*)(&P[(size_t)m0 * PN + n0])       = make_float2(acc[mi][ni][0], acc[mi][ni][1]);
            *(float2*)(&P[(size_t)(m0 + 8) * PN + n0]) = make_float2(acc[mi][ni][2], acc[mi][ni][3]);
        }
    }
}

// ---------------- finalize: partial-sum + bias + scales -> packed A2 ----------------
__global__ __launch_bounds__(256) void finalize_kernel(const float* __restrict__ bp)
{
    int b = blockIdx.x, c = threadIdx.x;
    int d, seg; colmap(c, d, seg);
    float v = 0.f;
    #pragma unroll
    for (int s = 0; s < PSPLIT; s++)
        v += Pp[((size_t)s * BS_ + b) * PN + d];
    v += bp[d];
    if (d == 0)       v *= INV_SQRT_N_;
    else if (d <= 64) v *= INV_SQRT_N_ * SQRT2_;
    __nv_bfloat16 h = __float2bfloat16_rn(v);
    __nv_bfloat16 out = (seg == 1) ? __float2bfloat16_rn(v - __bfloat162float(h)) : h;
    A2[(size_t)b * KPP + c] = out;
}

// ---------------- big GEMM: C = A2 @ B2^T  (K=256, 4 k-tiles) ----------------
#define GM 128
#define GN 128
#define GK 64
#define NIT (KPP / GK)          // 4
#define STG 32768               // per stage: A 16KB @ +0, B 16KB @ +16384

__global__ __launch_bounds__(256, 2) void gemm_kernel(float* __restrict__ C)
{
    extern __shared__ char sm[];
    const uint32_t sb = s2u(sm);
    const int tid = threadIdx.x, lane = tid & 31, wid = tid >> 5;
    const int wm = wid & 1, wn = wid >> 1;
    const int bm = blockIdx.y * GM, bn = blockIdx.x * GN;
    const char* gA = (const char*)(A2 + (size_t)bm * KPP);
    const char* gB = (const char*)(B2 + (size_t)bn * KPP);

    const int lrow = tid >> 3;
    const int lc = tid & 7;

    const int arow = wm * 64 + (lane & 15);
    const uint32_t arx = (uint32_t)((arow & 7) << 4);
    const uint32_t acb = (uint32_t)((lane >> 4) * 16);
    const int brow = wn * 32 + (lane & 7) + ((lane >> 4) & 1) * 8;
    const uint32_t brx = (uint32_t)((brow & 7) << 4);
    const uint32_t bcb = (uint32_t)(((lane >> 3) & 1) * 16);

    float acc[4][4][4] = {};

    auto load_tile = [&](int kt, int stg) {
        size_t koff = (size_t)kt * GK * 2;
        uint32_t base = sb + stg * STG;
        #pragma unroll
        for (int t = 0; t < 4; t++) {
            int row = lrow + t * 32;
            uint32_t so = (uint32_t)(row * 128 + lc * 16); so ^= (so >> 3) & 0x70;
            CP_ASYNC16(base + so,         gA + (size_t)row * (KPP*2) + koff + lc * 16);
            CP_ASYNC16(base + 16384 + so, gB + (size_t)row * (KPP*2) + koff + lc * 16);
        }
        CP_COMMIT();
    };

    load_tile(0, 0);
    load_tile(1, 1);

    int st = 0;
    for (int kt = 0; kt < NIT; kt++) {
        if (kt + 2 < NIT) { load_tile(kt + 2, (kt + 2) % 3); CP_WAIT(2); }
        else if (kt + 1 < NIT) CP_WAIT(1);
        else CP_WAIT(0);
        __syncthreads();

        const uint32_t ab = sb + st * STG;
        const uint32_t bb = ab + 16384;

        uint32_t af[2][4][4], bf[2][2][4];
        #pragma unroll
        for (int mi = 0; mi < 4; mi++)
            LDSM4(af[0][mi], ab + (uint32_t)((arow + mi * 16) * 128) + ((0 + acb) ^ arx));
        #pragma unroll
        for (int nb = 0; nb < 2; nb++)
            LDSM4(bf[0][nb], bb + (uint32_t)((brow + nb * 16) * 128) + ((0 + bcb) ^ brx));

        #pragma unroll
        for (int ks = 0; ks < 4; ks++) {
            const int cur = ks & 1, nxt = cur ^ 1;
            if (ks < 3) {
                #pragma unroll
                for (int mi = 0; mi < 4; mi++)
                    LDSM4(af[nxt][mi], ab + (uint32_t)((arow + mi * 16) * 128) + (((ks + 1) * 32 + acb) ^ arx));
                #pragma unroll
                for (int nb = 0; nb < 2; nb++)
                    LDSM4(bf[nxt][nb], bb + (uint32_t)((brow + nb * 16) * 128) + (((ks + 1) * 32 + bcb) ^ brx));
            }
            #pragma unroll
            for (int mi = 0; mi < 4; mi++)
                #pragma unroll
                for (int ni = 0; ni < 4; ni++) {
                    uint32_t bp[2] = { bf[cur][ni >> 1][(ni & 1) * 2], bf[cur][ni >> 1][(ni & 1) * 2 + 1] };
                    MMA16816(acc[mi][ni], af[cur][mi], bp);
                }
        }
        __syncthreads();
        st = (st + 1 == 3) ? 0 : st + 1;
    }

    #pragma unroll
    for (int mi = 0; mi < 4; mi++) {
        int m0 = bm + wm * 64 + mi * 16 + (lane >> 2);
        #pragma unroll
        for (int ni = 0; ni < 4; ni++) {
            int n0 = bn + wn * 32 + ni * 8 + (lane & 3) * 2;
            *(float2*)(&C[(size_t)m0 * NN_ + n0])       = make_float2(acc[mi][ni][0], acc[mi][ni][1]);
            *(float2*)(&C[(size_t)(m0 + 8) * NN_ + n0]) = make_float2(acc[mi][ni][2], acc[mi][ni][3]);
        }
    }
}

// ---------------- launch ----------------
extern "C" void kernel_launch(void* const* d_in, const int* in_sizes, int n_in,
                              void* d_out, int out_size)
{
    const float* x  = (const float*)d_in[0];
    const float* Wp = (const float*)d_in[1];
    const float* bp = (const float*)d_in[2];
    const float* Ws = (const float*)d_in[3];
    float* out = (float*)d_out;

    cudaFuncSetAttribute(gemm_kernel,     cudaFuncAttributeMaxDynamicSharedMemorySize, 3 * STG);
    cudaFuncSetAttribute(proj_mma_kernel, cudaFuncAttributeMaxDynamicSharedMemorySize, 2 * QSTG);

    prep_kernel<<<SPLITX_BLKS + SPLITW_BLKS + NN_, 256>>>(x, Wp, Ws);
    proj_mma_kernel<<<dim3(PSPLIT, BS_ / QM), 256, 2 * QSTG>>>();
    finalize_kernel<<<BS_, 256>>>(bp);
    gemm_kernel<<<dim3(NN_ / GN, BS_ / GM), 256, 3 * STG>>>(out);
}

// round 15
// speedup vs baseline: 2.4487x; 1.7138x over previous
#include <cuda_runtime.h>
#include <cuda_fp16.h>
#include <cstdint>

#define BS_     4096
#define IN_DIM_ 2048
#define NN_     16384
#define DTOT_   129
#define KG      128          // gemm K: 64 cos/sin + 64 slack (fp16), dc handled in epilogue
#define PK      2048
#define PN      192
#define PSPLIT  8
#define PCH     (PK / PSPLIT)
#define INV_SQRT_N_ 0.0078125f
#define SQRT2_      1.41421356237309515f

__device__ __half Xf[BS_ * PK];
__device__ __half Wf[PN * PK];
__device__ float  Pp[PSPLIT * BS_ * PN];
__device__ __half A2[BS_ * KG];
__device__ __half B2[NN_ * KG];
__device__ float  dc_buf[BS_];

// ---------------- PTX helpers ----------------
__device__ __forceinline__ uint32_t s2u(const void* p) {
    uint32_t a; asm("{.reg .u64 t; cvta.to.shared.u64 t,%1; cvt.u32.u64 %0,t;}" : "=r"(a) : "l"(p));
    return a;
}
#define CP_ASYNC16(dst, src) asm volatile("cp.async.cg.shared.global [%0], [%1], 16;" :: "r"(dst), "l"(src))
#define CP_COMMIT()          asm volatile("cp.async.commit_group;" ::: "memory")
#define CP_WAIT(n)           asm volatile("cp.async.wait_group %0;" :: "n"(n) : "memory")
#define LDSM4(r, addr) asm volatile("ldmatrix.sync.aligned.m8n8.x4.shared.b16 {%0,%1,%2,%3}, [%4];" \
    : "=r"((r)[0]), "=r"((r)[1]), "=r"((r)[2]), "=r"((r)[3]) : "r"(addr))
#define MMAF16(d, a, b) asm volatile( \
    "mma.sync.aligned.m16n8k16.row.col.f32.f16.f16.f32 " \
    "{%0,%1,%2,%3}, {%4,%5,%6,%7}, {%8,%9}, {%0,%1,%2,%3};" \
    : "+f"((d)[0]), "+f"((d)[1]), "+f"((d)[2]), "+f"((d)[3]) \
    : "r"((a)[0]), "r"((a)[1]), "r"((a)[2]), "r"((a)[3]), "r"((b)[0]), "r"((b)[1]))

union HF4 { __half h[4]; uint2 u; };

// ---------------- prep: x->fp16, W->fp16 (padded), build B2 fp16 ----------------
#define XBLK ((BS_ * PK / 4) / 256)     // 8192
#define WBLK ((PN * PK / 4) / 256)      // 384
#define BBLK (NN_ / 2)                  // 8192 (2 rows per block)

__global__ __launch_bounds__(256) void prep_kernel(const float* __restrict__ x,
                                                   const float* __restrict__ Wp,
                                                   const float* __restrict__ Ws)
{
    int blk = blockIdx.x, tid = threadIdx.x;
    if (blk < XBLK) {
        int id = blk * 256 + tid;
        float4 v = ((const float4*)x)[id];
        HF4 h;
        h.h[0] = __float2half_rn(v.x); h.h[1] = __float2half_rn(v.y);
        h.h[2] = __float2half_rn(v.z); h.h[3] = __float2half_rn(v.w);
        ((uint2*)Xf)[id] = h.u;
    } else if (blk < XBLK + WBLK) {
        int id = (blk - XBLK) * 256 + tid;
        int row = (id * 4) / PK;
        HF4 h;
        if (row < DTOT_) {
            float4 v = ((const float4*)Wp)[id];
            h.h[0] = __float2half_rn(v.x); h.h[1] = __float2half_rn(v.y);
            h.h[2] = __float2half_rn(v.z); h.h[3] = __float2half_rn(v.w);
        } else {
            h.h[0] = h.h[1] = h.h[2] = h.h[3] = __float2half_rn(0.f);
        }
        ((uint2*)Wf)[id] = h.u;
    } else {
        // B2: col c -> d = c+1 ; d 1..64 cos/sin, d 65..128 slack (Ws^T)
        int nb = blk - XBLK - WBLK;
        int n = nb * 2 + (tid >> 7);
        int c = tid & 127;
        int d = c + 1;
        float v;
        if (d < 65) {
            int j = (d + 1) >> 1;
            int m = (j * n) & (NN_ - 1);
            float t = (float)(2 * m) * (1.0f / (float)NN_);
            float s, cc; sincospif(t, &s, &cc);
            v = (d & 1) ? cc : s;
        } else v = Ws[(size_t)n * 64 + (d - 65)];
        B2[(size_t)n * KG + c] = __float2half_rn(v);
    }
}

// ---------------- proj via fp16 tensor cores (split-K x8) ----------------
#define QM 64
#define QSTG 32768      // per stage: A 8KB @ +0, B 24KB @ +8192

__global__ __launch_bounds__(256, 2) void proj_mma_kernel()
{
    extern __shared__ char sm[];
    const uint32_t sb = s2u(sm);
    const int tid = threadIdx.x, lane = tid & 31, wid = tid >> 5;
    const int wm = wid & 1, wn = wid >> 1;
    const int s = blockIdx.x;
    const int bm = blockIdx.y * QM;

    const int arow = wm * 32 + (lane & 15);
    const uint32_t arx = (uint32_t)((arow & 7) << 4);
    const uint32_t acb = (uint32_t)((lane >> 4) * 16);
    const int brow = wn * 48 + (lane & 7) + ((lane >> 4) & 1) * 8;
    const uint32_t brx = (uint32_t)((brow & 7) << 4);
    const uint32_t bcb = (uint32_t)(((lane >> 3) & 1) * 16);

    float acc[2][6][4] = {};

    auto load_tile = [&](int it, int stg) {
        int k0 = s * PCH + it * 64;
        const char* gA = (const char*)(Xf + (size_t)bm * PK + k0);
        const char* gB = (const char*)(Wf + k0);
        uint32_t base = sb + stg * QSTG;
        #pragma unroll
        for (int t = 0; t < 2; t++) {
            int id = tid + t * 256, row = id >> 3, c = id & 7;
            uint32_t so = (uint32_t)(row * 128 + c * 16); so ^= (so >> 3) & 0x70;
            CP_ASYNC16(base + so, gA + (size_t)row * (PK * 2) + c * 16);
        }
        #pragma unroll
        for (int t = 0; t < 6; t++) {
            int id = tid + t * 256, row = id >> 3, c = id & 7;
            uint32_t so = (uint32_t)(row * 128 + c * 16); so ^= (so >> 3) & 0x70;
            CP_ASYNC16(base + 8192 + so, gB + (size_t)row * (PK * 2) + c * 16);
        }
        CP_COMMIT();
    };

    load_tile(0, 0);
    for (int it = 0; it < 4; it++) {
        if (it + 1 < 4) { load_tile(it + 1, (it + 1) & 1); CP_WAIT(1); }
        else CP_WAIT(0);
        __syncthreads();
        const uint32_t ab = sb + (it & 1) * QSTG;
        const uint32_t bb = ab + 8192;
        #pragma unroll
        for (int ks = 0; ks < 4; ks++) {
            uint32_t af[2][4], bf[3][4];
            #pragma unroll
            for (int mi = 0; mi < 2; mi++)
                LDSM4(af[mi], ab + (uint32_t)((arow + mi * 16) * 128) + ((ks * 32 + acb) ^ arx));
            #pragma unroll
            for (int nb = 0; nb < 3; nb++)
                LDSM4(bf[nb], bb + (uint32_t)((brow + nb * 16) * 128) + ((ks * 32 + bcb) ^ brx));
            #pragma unroll
            for (int mi = 0; mi < 2; mi++)
                #pragma unroll
                for (int ni = 0; ni < 6; ni++) {
                    uint32_t bp[2] = { bf[ni >> 1][(ni & 1) * 2], bf[ni >> 1][(ni & 1) * 2 + 1] };
                    MMAF16(acc[mi][ni], af[mi], bp);
                }
        }
        __syncthreads();
    }

    float* P = Pp + (size_t)s * BS_ * PN;
    #pragma unroll
    for (int mi = 0; mi < 2; mi++) {
        int m0 = bm + wm * 32 + mi * 16 + (lane >> 2);
        #pragma unroll
        for (int ni = 0; ni < 6; ni++) {
            int n0 = wn * 48 + ni * 8 + (lane & 3) * 2;
            *(float2*)(&P[(size_t)m0 * PN + n0])       = make_float2(acc[mi][ni][0], acc[mi][ni][1]);
            *(float2*)(&P[(size_t)(m0 + 8) * PN + n0]) = make_float2(acc[mi][ni][2], acc[mi][ni][3]);
        }
    }
}

// ---------------- finalize: partial-sum + bias + scales -> A2 fp16, dc fp32 ----------------
__global__ __launch_bounds__(256) void finalize_kernel(const float* __restrict__ bp)
{
    int b = blockIdx.x, d = threadIdx.x;
    if (d >= DTOT_) return;
    float v = 0.f;
    #pragma unroll
    for (int s = 0; s < PSPLIT; s++)
        v += Pp[((size_t)s * BS_ + b) * PN + d];
    v += bp[d];
    if (d == 0) {
        dc_buf[b] = v * INV_SQRT_N_;            // exact fp32, added in gemm epilogue
    } else {
        if (d <= 64) v *= INV_SQRT_N_ * SQRT2_;
        A2[(size_t)b * KG + (d - 1)] = __float2half_rn(v);
    }
}

// ---------------- big GEMM: C = A2 @ B2^T + dc (K=128, 2 k-tiles) ----------------
#define GM 128
#define GN 128
#define GK 64
#define NIT 2
#define STG 32768               // per stage: A 16KB @ +0, B 16KB @ +16384

__global__ __launch_bounds__(256, 2) void gemm_kernel(float* __restrict__ C)
{
    extern __shared__ char sm[];
    const uint32_t sb = s2u(sm);
    const int tid = threadIdx.x, lane = tid & 31, wid = tid >> 5;
    const int wm = wid & 1, wn = wid >> 1;
    const int bm = blockIdx.y * GM, bn = blockIdx.x * GN;
    const char* gA = (const char*)(A2 + (size_t)bm * KG);
    const char* gB = (const char*)(B2 + (size_t)bn * KG);

    const int lrow = tid >> 3;
    const int lc = tid & 7;

    const int arow = wm * 64 + (lane & 15);
    const uint32_t arx = (uint32_t)((arow & 7) << 4);
    const uint32_t acb = (uint32_t)((lane >> 4) * 16);
    const int brow = wn * 32 + (lane & 7) + ((lane >> 4) & 1) * 8;
    const uint32_t brx = (uint32_t)((brow & 7) << 4);
    const uint32_t bcb = (uint32_t)(((lane >> 3) & 1) * 16);

    float acc[4][4][4] = {};

    auto load_tile = [&](int kt, int stg) {
        size_t koff = (size_t)kt * GK * 2;
        uint32_t base = sb + stg * STG;
        #pragma unroll
        for (int t = 0; t < 4; t++) {
            int row = lrow + t * 32;
            uint32_t so = (uint32_t)(row * 128 + lc * 16); so ^= (so >> 3) & 0x70;
            CP_ASYNC16(base + so,         gA + (size_t)row * (KG*2) + koff + lc * 16);
            CP_ASYNC16(base + 16384 + so, gB + (size_t)row * (KG*2) + koff + lc * 16);
        }
        CP_COMMIT();
    };

    load_tile(0, 0);
    load_tile(1, 1);

    #pragma unroll
    for (int kt = 0; kt < NIT; kt++) {
        if (kt == 0) CP_WAIT(1); else CP_WAIT(0);
        __syncthreads();

        const uint32_t ab = sb + kt * STG;
        const uint32_t bb = ab + 16384;

        uint32_t af[2][4][4], bf[2][2][4];
        #pragma unroll
        for (int mi = 0; mi < 4; mi++)
            LDSM4(af[0][mi], ab + (uint32_t)((arow + mi * 16) * 128) + ((0 + acb) ^ arx));
        #pragma unroll
        for (int nb = 0; nb < 2; nb++)
            LDSM4(bf[0][nb], bb + (uint32_t)((brow + nb * 16) * 128) + ((0 + bcb) ^ brx));

        #pragma unroll
        for (int ks = 0; ks < 4; ks++) {
            const int cur = ks & 1, nxt = cur ^ 1;
            if (ks < 3) {
                #pragma unroll
                for (int mi = 0; mi < 4; mi++)
                    LDSM4(af[nxt][mi], ab + (uint32_t)((arow + mi * 16) * 128) + (((ks + 1) * 32 + acb) ^ arx));
                #pragma unroll
                for (int nb = 0; nb < 2; nb++)
                    LDSM4(bf[nxt][nb], bb + (uint32_t)((brow + nb * 16) * 128) + (((ks + 1) * 32 + bcb) ^ brx));
            }
            #pragma unroll
            for (int mi = 0; mi < 4; mi++)
                #pragma unroll
                for (int ni = 0; ni < 4; ni++) {
                    uint32_t bp[2] = { bf[cur][ni >> 1][(ni & 1) * 2], bf[cur][ni >> 1][(ni & 1) * 2 + 1] };
                    MMAF16(acc[mi][ni], af[cur][mi], bp);
                }
        }
    }

    // epilogue: + dc (exact fp32), store
    #pragma unroll
    for (int mi = 0; mi < 4; mi++) {
        int m0 = bm + wm * 64 + mi * 16 + (lane >> 2);
        float dc0 = dc_buf[m0], dc1 = dc_buf[m0 + 8];
        #pragma unroll
        for (int ni = 0; ni < 4; ni++) {
            int n0 = bn + wn * 32 + ni * 8 + (lane & 3) * 2;
            *(float2*)(&C[(size_t)m0 * NN_ + n0]) =
                make_float2(acc[mi][ni][0] + dc0, acc[mi][ni][1] + dc0);
            *(float2*)(&C[(size_t)(m0 + 8) * NN_ + n0]) =
                make_float2(acc[mi][ni][2] + dc1, acc[mi][ni][3] + dc1);
        }
    }
}

// ---------------- launch ----------------
extern "C" void kernel_launch(void* const* d_in, const int* in_sizes, int n_in,
                              void* d_out, int out_size)
{
    const float* x  = (const float*)d_in[0];
    const float* Wp = (const float*)d_in[1];
    const float* bp = (const float*)d_in[2];
    const float* Ws = (const float*)d_in[3];
    float* out = (float*)d_out;

    cudaFuncSetAttribute(gemm_kernel,     cudaFuncAttributeMaxDynamicSharedMemorySize, 2 * STG);
    cudaFuncSetAttribute(proj_mma_kernel, cudaFuncAttributeMaxDynamicSharedMemorySize, 2 * QSTG);

    prep_kernel<<<XBLK + WBLK + BBLK, 256>>>(x, Wp, Ws);
    proj_mma_kernel<<<dim3(PSPLIT, BS_ / QM), 256, 2 * QSTG>>>();
    finalize_kernel<<<BS_, 256>>>(bp);
    gemm_kernel<<<dim3(NN_ / GN, BS_ / GM), 256, 2 * STG>>>(out);
}